// round 7
// baseline (speedup 1.0000x reference)
#include <cuda_runtime.h>
#include <cstdint>

// MaxUnpooling2D: updates [16,64,64,256] f32, mask [16,64,64,256] i32 (flat idx
// into [16,128,128,256]), out [16,128,128,256] f32.
//
// Each pooled cell targets exactly one slot of its private 2x2 window -> no
// duplicates -> plain stores; zero-fill fused (thread writes all 4 window
// positions for its 4 channels). Depth-1, one float4-group per thread — the
// measured-best skeleton (R1: 59.1us kernel, DRAM 71.7%).
//
// R7: single unconfounded change vs R1 — block size 256 -> 512 (launch_bounds
// 512,4; still 64 warps/SM). A block now covers 8 consecutive w-windows, so
// its store footprint per output row is 16KB contiguous (vs 8KB), coarsening
// the per-scheduling-quantum DRAM write runs. Everything else identical.

namespace {
constexpr int ROW   = 2 * 64 * 256;       // 32768  (dy=1 stride in out)
constexpr int COLS  = 256;                // dx=1 stride in out
constexpr int IMG   = 2 * 64 * ROW;       // batch stride in out
constexpr int NGROUPS = 16 * 64 * 64 * (256 / 4);   // 4,194,304 float4 groups
constexpr int THREADS = 512;
constexpr int BLOCKS  = NGROUPS / THREADS;          // 8192
}

__global__ void __launch_bounds__(THREADS, 4)
max_unpool_kernel(const float4* __restrict__ upd,
                  const int4*  __restrict__ mask,
                  float*       __restrict__ out)
{
    int t = blockIdx.x * THREADS + threadIdx.x;

    // t = ((b*64 + h)*64 + w)*64 + c4
    int c4 = t & 63;
    int w  = (t >> 6)  & 63;
    int h  = (t >> 12) & 63;
    int b  = t >> 18;
    int c  = c4 << 2;

    // Flat output index of window origin (2h, 2w) at channel c.
    int o00 = b * IMG + (h << 1) * ROW + (w << 1) * COLS + c;

    float4 v = upd[t];
    int4   m = mask[t];

    // Per-lane offset within window: in {0, COLS, ROW, ROW+COLS}
    int d0 = m.x - o00;
    int d1 = m.y - o00 - 1;
    int d2 = m.z - o00 - 2;
    int d3 = m.w - o00 - 3;

    float4 r00 = make_float4(d0 == 0          ? v.x : 0.f,
                             d1 == 0          ? v.y : 0.f,
                             d2 == 0          ? v.z : 0.f,
                             d3 == 0          ? v.w : 0.f);
    float4 r01 = make_float4(d0 == COLS       ? v.x : 0.f,
                             d1 == COLS       ? v.y : 0.f,
                             d2 == COLS       ? v.z : 0.f,
                             d3 == COLS       ? v.w : 0.f);
    float4 r10 = make_float4(d0 == ROW        ? v.x : 0.f,
                             d1 == ROW        ? v.y : 0.f,
                             d2 == ROW        ? v.z : 0.f,
                             d3 == ROW        ? v.w : 0.f);
    float4 r11 = make_float4(d0 == ROW + COLS ? v.x : 0.f,
                             d1 == ROW + COLS ? v.y : 0.f,
                             d2 == ROW + COLS ? v.z : 0.f,
                             d3 == ROW + COLS ? v.w : 0.f);

    *reinterpret_cast<float4*>(out + o00)              = r00;
    *reinterpret_cast<float4*>(out + o00 + COLS)       = r01;
    *reinterpret_cast<float4*>(out + o00 + ROW)        = r10;
    *reinterpret_cast<float4*>(out + o00 + ROW + COLS) = r11;
}

extern "C" void kernel_launch(void* const* d_in, const int* in_sizes, int n_in,
                              void* d_out, int out_size)
{
    const float4* upd  = reinterpret_cast<const float4*>(d_in[0]);
    const int4*   mask = reinterpret_cast<const int4*>(d_in[1]);
    float*        out  = reinterpret_cast<float*>(d_out);

    max_unpool_kernel<<<BLOCKS, THREADS>>>(upd, mask, out);
}

// round 8
// speedup vs baseline: 1.0312x; 1.0312x over previous
#include <cuda_runtime.h>
#include <cstdint>

// MaxUnpooling2D: updates [16,64,64,256] f32, mask [16,64,64,256] i32 (flat idx
// into [16,128,128,256]), out [16,128,128,256] f32.
//
// Each pooled cell targets exactly one slot of its private 2x2 window -> no
// duplicates -> plain stores; zero-fill fused.
//
// R8: isolate per-warp WRITE-STREAM count. One thread = one window ROW
// (ry in {0,1}) of a cell's 4 channels: 2 loads, 2 float4 stores into a
// single output row (1KB apart) — vs R1's 4 stores spanning 2 rows 128KB
// apart. Inputs are read twice, but the sibling thread is in the same block
// so the duplicate read hits L1/L2; DRAM reads stay 128MB. Tests whether the
// ~71% DRAM plateau is row-interleave-limited.

namespace {
constexpr int ROW   = 2 * 64 * 256;       // 32768  (dy=1 stride in out)
constexpr int COLS  = 256;                // dx=1 stride in out
constexpr int IMG   = 2 * 64 * ROW;       // batch stride in out
constexpr int NTHREADS_TOTAL = 16 * 64 * 64 * 2 * (256 / 4);  // 8,388,608
constexpr int THREADS = 256;
constexpr int BLOCKS  = NTHREADS_TOTAL / THREADS;             // 32768
}

__global__ void __launch_bounds__(THREADS, 8)
max_unpool_kernel(const float4* __restrict__ upd,
                  const int4*  __restrict__ mask,
                  float*       __restrict__ out)
{
    int t = blockIdx.x * THREADS + threadIdx.x;

    // t = (((b*64 + h)*64 + w)*2 + ry)*64 + c4
    int c4 = t & 63;
    int ry = (t >> 6) & 1;
    int w  = (t >> 7)  & 63;
    int h  = (t >> 13) & 63;
    int b  = t >> 19;
    int c  = c4 << 2;

    // Input group index (cell, c4): g = ((b*64+h)*64 + w)*64 + c4
    int g = ((t >> 7) << 6) | c4;

    // Window-origin flat index and this thread's row offset.
    int o00  = b * IMG + (h << 1) * ROW + (w << 1) * COLS + c;
    int sel  = ry * ROW;                 // 0 or ROW
    int obase = o00 + sel;

    float4 v = upd[g];
    int4   m = mask[g];

    // Per-lane offset within window: in {0, COLS, ROW, ROW+COLS}
    int d0 = m.x - o00;
    int d1 = m.y - o00 - 1;
    int d2 = m.z - o00 - 2;
    int d3 = m.w - o00 - 3;

    float4 rA = make_float4(d0 == sel        ? v.x : 0.f,
                            d1 == sel        ? v.y : 0.f,
                            d2 == sel        ? v.z : 0.f,
                            d3 == sel        ? v.w : 0.f);
    float4 rB = make_float4(d0 == sel + COLS ? v.x : 0.f,
                            d1 == sel + COLS ? v.y : 0.f,
                            d2 == sel + COLS ? v.z : 0.f,
                            d3 == sel + COLS ? v.w : 0.f);

    *reinterpret_cast<float4*>(out + obase)        = rA;
    *reinterpret_cast<float4*>(out + obase + COLS) = rB;
}

extern "C" void kernel_launch(void* const* d_in, const int* in_sizes, int n_in,
                              void* d_out, int out_size)
{
    const float4* upd  = reinterpret_cast<const float4*>(d_in[0]);
    const int4*   mask = reinterpret_cast<const int4*>(d_in[1]);
    float*        out  = reinterpret_cast<float*>(d_out);

    max_unpool_kernel<<<BLOCKS, THREADS>>>(upd, mask, out);
}